// round 9
// baseline (speedup 1.0000x reference)
#include <cuda_runtime.h>
#include <cstdint>
#include <cstddef>

#define N_USERS   100000
#define N_NODES   500000
#define DIM       64
#define N_EDGES   2000000
#define BATCH     4096

// -------- device scratch (static, allocation-free) --------
// NOTE: never touch these symbols from host code (GB300 ATS would silently
// route through the host shadow at 200GB/s). All access via device selectors.
__device__ float    g_XA[(size_t)N_NODES * DIM];
__device__ float    g_XB[(size_t)N_NODES * DIM];
__device__ float    g_XC[(size_t)N_NODES * DIM];
__device__ float    g_dinv[N_NODES];
__device__ unsigned g_deg[N_NODES];
__device__ int      g_f[3][N_NODES];       // needed-node flags (0=L1,1=L2,2=L3)
__device__ int      g_nl[3][N_NODES];      // compact node lists
__device__ int      g_ncnt[3];
__device__ int2     g_le[3][N_EDGES];      // compact edge lists (src,dst); [0] unused
__device__ int      g_ecnt[3];

__device__ __forceinline__ float* xbuf(int sel) {
    return sel == 1 ? g_XA : (sel == 2 ? g_XB : g_XC);
}

// -------- init counters + flags --------
__global__ void k_init() {
    int i = blockIdx.x * blockDim.x + threadIdx.x;
    if (i < N_NODES) {
        g_deg[i] = 0u;
        g_f[0][i] = 0; g_f[1][i] = 0; g_f[2][i] = 0;
    }
    if (i < 3) { g_ncnt[i] = 0; g_ecnt[i] = 0; }
}

__global__ void k_deg(const int* __restrict__ dst) {
    int e = blockIdx.x * blockDim.x + threadIdx.x;
    if (e < N_EDGES) atomicAdd(&g_deg[dst[e]], 1u);
}

__global__ void k_dinv() {
    int i = blockIdx.x * blockDim.x + threadIdx.x;
    if (i < N_NODES) {
        unsigned d = g_deg[i];
        g_dinv[i] = d ? rsqrtf((float)d) : 0.0f;
    }
}

// warp-aggregated list append: returns this lane's slot (valid where pred)
__device__ __forceinline__ int wagg_append(int* counter, bool pred) {
    unsigned mask = __ballot_sync(0xffffffffu, pred);
    if (!pred) return -1;
    int lane   = threadIdx.x & 31;
    int leader = __ffs(mask) - 1;
    int rank   = __popc(mask & ((1u << lane) - 1));
    int base = 0;
    if (lane == leader) base = atomicAdd(counter, __popc(mask));
    base = __shfl_sync(mask, base, leader);
    return base + rank;
}

// mark batch nodes in all 3 flag sets + node lists; one (layer, slot) per thread
__global__ void k_mark_batch(const int* __restrict__ u,
                             const int* __restrict__ p,
                             const int* __restrict__ n) {
    int t = blockIdx.x * blockDim.x + threadIdx.x;
    bool act = (t < 9 * BATCH);
    int L = 0, idx = 0;
    if (act) {
        L = t / (3 * BATCH);
        int r = t - L * (3 * BATCH);
        idx = (r < BATCH) ? u[r]
            : (r < 2 * BATCH) ? p[r - BATCH]
                              : n[r - 2 * BATCH];
        act = (atomicExch(&g_f[L][idx], 1) == 0);
    }
#pragma unroll
    for (int LL = 0; LL < 3; LL++) {
        bool pred = act && (L == LL);
        int slot = wagg_append(&g_ncnt[LL], pred);
        if (pred) g_nl[LL][slot] = idx;
    }
}

// compaction, 4 edges per thread (int4 loads -> MLP=4 on the flag gathers):
// gate on f[gate], append passing edges to list[gate]; mark sources one layer
// earlier (+node list).
__global__ void k_compact4(const int* __restrict__ src, const int* __restrict__ dst,
                           int gate, int prev) {
    int t = blockIdx.x * blockDim.x + threadIdx.x;
    bool inb = (t < N_EDGES / 4);
    int4 d4 = make_int4(0, 0, 0, 0);
    if (inb) d4 = __ldg((const int4*)dst + t);
    const int dd[4] = {d4.x, d4.y, d4.z, d4.w};
    bool p[4];
#pragma unroll
    for (int i = 0; i < 4; i++)
        p[i] = inb && (g_f[gate][dd[i]] != 0);

    int4 s4 = make_int4(0, 0, 0, 0);
    if (p[0] | p[1] | p[2] | p[3]) s4 = __ldg((const int4*)src + t);
    const int ss[4] = {s4.x, s4.y, s4.z, s4.w};

#pragma unroll
    for (int i = 0; i < 4; i++) {
        int slot = wagg_append(&g_ecnt[gate], p[i]);
        if (p[i]) g_le[gate][slot] = make_int2(ss[i], dd[i]);
    }
#pragma unroll
    for (int i = 0; i < 4; i++) {
        bool nw = p[i] && (atomicExch(&g_f[prev][ss[i]], 1) == 0);
        int ns = wagg_append(&g_ncnt[prev], nw);
        if (nw) g_nl[prev][ns] = ss[i];
    }
}

// zero exactly the rows in node list lsel of buffer xsel (grid-stride)
__global__ void k_zero_list(int xsel, int lsel) {
    int n16 = g_ncnt[lsel] * 16;
    float4* y = (float4*)xbuf(xsel);
    int stride = gridDim.x * blockDim.x;
    for (int t = blockIdx.x * blockDim.x + threadIdx.x; t < n16; t += stride) {
        int node = g_nl[lsel][t >> 4];
        y[(size_t)node * 16 + (t & 15)] = make_float4(0.f, 0.f, 0.f, 0.f);
    }
}

// fused layer-1: scan ALL edges, gate on f[0], gather emb -> RED into XA.
// 16 lanes per edge; lanes 0/16 load dst/flag/src and broadcast (all shuffles
// issued while the full warp is converged, BEFORE any divergent exit).
__global__ void k_prop1(const float* __restrict__ emb,
                        const int* __restrict__ src, const int* __restrict__ dst) {
    unsigned gid = blockIdx.x * blockDim.x + threadIdx.x;
    unsigned e = gid >> 4;                    // grid is an exact multiple of 16
    int lane = threadIdx.x & 31;
    int l16  = lane & 15;
    int bl   = lane & 16;                     // broadcast source lane: 0 or 16
    int d = 0, f = 0, s = 0;
    if (l16 == 0) {
        d = __ldg(dst + e);
        f = g_f[0][d];
        if (f) s = __ldg(src + e);
    }
    d = __shfl_sync(0xffffffffu, d, bl);
    f = __shfl_sync(0xffffffffu, f, bl);
    s = __shfl_sync(0xffffffffu, s, bl);
    if (!f) return;

    float w = __ldg(g_dinv + s) * __ldg(g_dinv + d);
    float4 v = __ldg((const float4*)emb + (size_t)s * 16 + l16);
    float4* a = (float4*)g_XA + (size_t)d * 16 + l16;
    asm volatile("red.global.add.v4.f32 [%0], {%1, %2, %3, %4};"
                 :: "l"(a), "f"(v.x * w), "f"(v.y * w), "f"(v.z * w), "f"(v.w * w)
                 : "memory");
}

// propagation over compact edge list: 16 threads/edge, grid-stride.
__global__ void k_prop_list(int xsel, int ysel, int lsel) {
    int m = g_ecnt[lsel] * 16;
    const float* x = xbuf(xsel);
    float*       y = xbuf(ysel);
    int stride = gridDim.x * blockDim.x;
    for (int t = blockIdx.x * blockDim.x + threadIdx.x; t < m; t += stride) {
        int e = t >> 4, lane = t & 15;
        int2  sd = __ldg(&g_le[lsel][e]);
        float w = __ldg(g_dinv + sd.x) * __ldg(g_dinv + sd.y);
        float4 v = __ldg((const float4*)x + (size_t)sd.x * 16 + lane);
        float4* a = (float4*)y + (size_t)sd.y * 16 + lane;
        asm volatile("red.global.add.v4.f32 [%0], {%1, %2, %3, %4};"
                     :: "l"(a), "f"(v.x * w), "f"(v.y * w), "f"(v.z * w), "f"(v.w * w)
                     : "memory");
    }
}

__global__ void k_zero_out(float* out) {
    if (threadIdx.x == 0 && blockIdx.x == 0) out[0] = 0.0f;
}

// -------- fused final loss: one warp per batch element --------
__global__ void k_loss(const float* __restrict__ emb,
                       const int* __restrict__ user,
                       const int* __restrict__ pos,
                       const int* __restrict__ neg,
                       float* __restrict__ out) {
    int w = (blockIdx.x * blockDim.x + threadIdx.x) >> 5;
    int lane = threadIdx.x & 31;
    if (w >= BATCH) return;

    int ui = user[w], pi = pos[w], ni = neg[w];

    const float2* E = (const float2*)emb;
    const float2* A = (const float2*)g_XA;
    const float2* B = (const float2*)g_XB;
    const float2* C = (const float2*)g_XC;

    size_t uo = (size_t)ui * 32 + lane;
    size_t po = (size_t)pi * 32 + lane;
    size_t no = (size_t)ni * 32 + lane;

    float2 eu = __ldg(E + uo), ep = __ldg(E + po), en = __ldg(E + no);
    float2 au = __ldg(A + uo), bu = __ldg(B + uo), cu = __ldg(C + uo);
    float2 ap = __ldg(A + po), bp = __ldg(B + po), cp = __ldg(C + po);
    float2 an = __ldg(A + no), bn = __ldg(B + no), cn = __ldg(C + no);

    float ux = eu.x + au.x + bu.x + cu.x, uy = eu.y + au.y + bu.y + cu.y;
    float px = ep.x + ap.x + bp.x + cp.x, py = ep.y + ap.y + bp.y + cp.y;
    float nx = en.x + an.x + bn.x + cn.x, ny = en.y + an.y + bn.y + cn.y;

    float pd = ux * px + uy * py;
    float nd = ux * nx + uy * ny;
    float sq = eu.x * eu.x + eu.y * eu.y
             + ep.x * ep.x + ep.y * ep.y
             + en.x * en.x + en.y * en.y;

#pragma unroll
    for (int o = 16; o; o >>= 1) {
        pd += __shfl_xor_sync(0xffffffffu, pd, o);
        nd += __shfl_xor_sync(0xffffffffu, nd, o);
        sq += __shfl_xor_sync(0xffffffffu, sq, o);
    }
    if (lane == 0) {
        float z = (nd - pd) * 0.0625f;                       // /16 for mean^2
        float sp = fmaxf(z, 0.f) + log1pf(expf(-fabsf(z)));  // softplus(neg-pos)
        atomicAdd(out, (sp + 5e-5f * sq) * (1.0f / BATCH));  // + L2_REG*0.5/BATCH
    }
}

extern "C" void kernel_launch(void* const* d_in, const int* in_sizes, int n_in,
                              void* d_out, int out_size) {
    const float* emb  = (const float*)d_in[0];
    const int*   edge = (const int*)d_in[1];
    const int*   src  = edge;
    const int*   dst  = edge + N_EDGES;
    const int*   user = (const int*)d_in[2];
    const int*   pos  = (const int*)d_in[3];
    const int*   neg  = (const int*)d_in[4];
    float*       out  = (float*)d_out;

    static cudaStream_t s1 = nullptr, s2 = nullptr;
    static cudaEvent_t evInit, evMark, evA, evB, evDinv, evZ;
    if (!s1) {
        cudaStreamCreateWithFlags(&s1, cudaStreamNonBlocking);
        cudaStreamCreateWithFlags(&s2, cudaStreamNonBlocking);
        cudaEventCreateWithFlags(&evInit, cudaEventDisableTiming);
        cudaEventCreateWithFlags(&evMark, cudaEventDisableTiming);
        cudaEventCreateWithFlags(&evA,    cudaEventDisableTiming);
        cudaEventCreateWithFlags(&evB,    cudaEventDisableTiming);
        cudaEventCreateWithFlags(&evDinv, cudaEventDisableTiming);
        cudaEventCreateWithFlags(&evZ,    cudaEventDisableTiming);
    }

    const int T = 256;
    const int G_NODES = (N_NODES + T - 1) / T;
    const int G_EDGES = (N_EDGES + T - 1) / T;
    const int G_CMP4  = (N_EDGES / 4 + T - 1) / T;
    const int G_MARK  = (9 * BATCH + T - 1) / T;
    const int G_P1    = (int)((size_t)N_EDGES * 16 / T);   // exact: 125000 blocks
    const int G_PROP  = 2048;
    const int G_ZERO  = 1024;

    // origin stream: the serial critical chain (init -> mark -> compact x2)
    k_init<<<G_NODES, T>>>();
    cudaEventRecord(evInit, 0);
    k_mark_batch<<<G_MARK, T>>>(user, pos, neg);
    cudaEventRecord(evMark, 0);
    k_compact4<<<G_CMP4, T>>>(src, dst, 2, 1);      // L3 edges -> list2; mark f1 (+nl1)
    cudaEventRecord(evA, 0);
    k_compact4<<<G_CMP4, T>>>(src, dst, 1, 0);      // L2 edges -> list1; mark f0 (+nl0)
    cudaEventRecord(evB, 0);

    // side chain (s1): deg -> dinv, needed only by the props; starts after init
    cudaStreamWaitEvent(s1, evInit, 0);
    k_deg<<<G_EDGES, T, 0, s1>>>(dst);
    k_dinv<<<G_NODES, T, 0, s1>>>();
    cudaEventRecord(evDinv, s1);

    // side chain (s2): joins capture via event-wait BEFORE any launch
    cudaStreamWaitEvent(s2, evMark, 0);
    k_zero_out<<<1, 1, 0, s2>>>(out);
    k_zero_list<<<G_ZERO, T, 0, s2>>>(3, 2);        // XC over nl2 (final at mark)
    cudaStreamWaitEvent(s2, evA, 0);
    k_zero_list<<<G_ZERO, T, 0, s2>>>(2, 1);        // XB over nl1 (final at compactA)
    cudaStreamWaitEvent(s2, evB, 0);
    k_zero_list<<<G_ZERO, T, 0, s2>>>(1, 0);        // XA over nl0 (final at compactB)
    cudaEventRecord(evZ, s2);

    // join side chains onto origin before the props
    cudaStreamWaitEvent(0, evDinv, 0);
    cudaStreamWaitEvent(0, evZ, 0);

    // layer 1 fused with compaction: scan all edges gated on f0, emb -> XA
    k_prop1<<<G_P1, T>>>(emb, src, dst);
    // layers 2/3 over compact lists
    k_prop_list<<<G_PROP, T>>>(1, 2, 1);            // XA -> XB over list1
    k_prop_list<<<G_PROP, T>>>(2, 3, 2);            // XB -> XC over list2

    // fused loss (out zeroed on s2, ordered via evZ)
    k_loss<<<BATCH / 8, T>>>(emb, user, pos, neg, out);
}

// round 10
// speedup vs baseline: 1.4733x; 1.4733x over previous
#include <cuda_runtime.h>
#include <cstdint>
#include <cstddef>

#define N_USERS   100000
#define N_NODES   500000
#define DIM       64
#define N_EDGES   2000000
#define BATCH     4096
#define NWORDS    ((N_NODES + 31) / 32)    // 15625 words per bitmask

// -------- device scratch (static, allocation-free) --------
// NOTE: never touch these symbols from host code (GB300 ATS would silently
// route through the host shadow at 200GB/s). All access via device selectors.
__device__ float    g_XA[(size_t)N_NODES * DIM];
__device__ float    g_XB[(size_t)N_NODES * DIM];
__device__ float    g_XC[(size_t)N_NODES * DIM];
__device__ float    g_dinv[N_NODES];
__device__ unsigned g_deg[N_NODES];
__device__ unsigned g_fb[3][NWORDS];       // needed-node BITMASKS (L2-resident, 62.5KB ea)
__device__ int      g_nl[3][N_NODES];      // compact node lists
__device__ int      g_ncnt[3];
__device__ int2     g_le[3][N_EDGES];      // compact edge lists (src,dst)
__device__ int      g_ecnt[3];

__device__ __forceinline__ float* xbuf(int sel) {
    return sel == 1 ? g_XA : (sel == 2 ? g_XB : g_XC);
}

// -------- init counters + flag bitmasks --------
__global__ void k_init() {
    int i = blockIdx.x * blockDim.x + threadIdx.x;
    if (i < N_NODES) g_deg[i] = 0u;
    if (i < NWORDS) { g_fb[0][i] = 0u; g_fb[1][i] = 0u; g_fb[2][i] = 0u; }
    if (i < 3) { g_ncnt[i] = 0; g_ecnt[i] = 0; }
}

__global__ void k_deg(const int* __restrict__ dst) {
    int e = blockIdx.x * blockDim.x + threadIdx.x;
    if (e < N_EDGES) atomicAdd(&g_deg[dst[e]], 1u);
}

__global__ void k_dinv() {
    int i = blockIdx.x * blockDim.x + threadIdx.x;
    if (i < N_NODES) {
        unsigned d = g_deg[i];
        g_dinv[i] = d ? rsqrtf((float)d) : 0.0f;
    }
}

// warp-aggregated list append: returns this lane's slot (valid where pred)
__device__ __forceinline__ int wagg_append(int* counter, bool pred) {
    unsigned mask = __ballot_sync(0xffffffffu, pred);
    if (!pred) return -1;
    int lane   = threadIdx.x & 31;
    int leader = __ffs(mask) - 1;
    int rank   = __popc(mask & ((1u << lane) - 1));
    int base = 0;
    if (lane == leader) base = atomicAdd(counter, __popc(mask));
    base = __shfl_sync(mask, base, leader);
    return base + rank;
}

// set bit idx in mask L; true if newly set (dedup)
__device__ __forceinline__ bool mark_node(int L, int idx) {
    unsigned bit = 1u << (idx & 31);
    unsigned old = atomicOr(&g_fb[L][idx >> 5], bit);
    return (old & bit) == 0u;
}

__device__ __forceinline__ bool test_node(int L, int idx) {
    return (g_fb[L][idx >> 5] >> (idx & 31)) & 1u;
}

// mark batch nodes in all 3 bitmasks + node lists; one (layer, slot) per thread
__global__ void k_mark_batch(const int* __restrict__ u,
                             const int* __restrict__ p,
                             const int* __restrict__ n) {
    int t = blockIdx.x * blockDim.x + threadIdx.x;
    bool act = (t < 9 * BATCH);
    int L = 0, idx = 0;
    if (act) {
        L = t / (3 * BATCH);
        int r = t - L * (3 * BATCH);
        idx = (r < BATCH) ? u[r]
            : (r < 2 * BATCH) ? p[r - BATCH]
                              : n[r - 2 * BATCH];
        act = mark_node(L, idx);
    }
#pragma unroll
    for (int LL = 0; LL < 3; LL++) {
        bool pred = act && (L == LL);
        int slot = wagg_append(&g_ncnt[LL], pred);
        if (pred) g_nl[LL][slot] = idx;
    }
}

// compaction: gate on bitmask[gate] (L2-resident), append passing edges to
// list[gate]; optionally mark sources one layer earlier (+node list)
__global__ void k_compact(const int* __restrict__ src, const int* __restrict__ dst,
                          int gate, int prev, int has_prev) {
    int e = blockIdx.x * blockDim.x + threadIdx.x;
    bool pass = false;
    int s = 0, d = 0;
    if (e < N_EDGES) {
        d = __ldg(dst + e);
        pass = test_node(gate, d);
        if (pass) s = __ldg(src + e);
    }
    int slot = wagg_append(&g_ecnt[gate], pass);
    if (pass) g_le[gate][slot] = make_int2(s, d);

    if (has_prev) {
        bool nw = pass && mark_node(prev, s);
        int ns = wagg_append(&g_ncnt[prev], nw);
        if (nw) g_nl[prev][ns] = s;
    }
}

// zero exactly the rows in node list lsel of buffer xsel (grid-stride)
__global__ void k_zero_list(int xsel, int lsel) {
    int n16 = g_ncnt[lsel] * 16;
    float4* y = (float4*)xbuf(xsel);
    int stride = gridDim.x * blockDim.x;
    for (int t = blockIdx.x * blockDim.x + threadIdx.x; t < n16; t += stride) {
        int node = g_nl[lsel][t >> 4];
        y[(size_t)node * 16 + (t & 15)] = make_float4(0.f, 0.f, 0.f, 0.f);
    }
}

// propagation over compact edge list: 16 threads/edge, grid-stride.
// weight computed on the fly from L2-resident dinv (broadcast across lanes).
__global__ void k_prop_list(const float* __restrict__ emb, int xsel, int ysel, int lsel) {
    int m = g_ecnt[lsel] * 16;
    const float* x = (xsel == 0) ? emb : xbuf(xsel);
    float*       y = xbuf(ysel);
    int stride = gridDim.x * blockDim.x;
    for (int t = blockIdx.x * blockDim.x + threadIdx.x; t < m; t += stride) {
        int e = t >> 4, lane = t & 15;
        int2  sd = __ldg(&g_le[lsel][e]);
        float w = __ldg(g_dinv + sd.x) * __ldg(g_dinv + sd.y);
        float4 v = __ldg((const float4*)x + (size_t)sd.x * 16 + lane);
        float4* a = (float4*)y + (size_t)sd.y * 16 + lane;
        asm volatile("red.global.add.v4.f32 [%0], {%1, %2, %3, %4};"
                     :: "l"(a), "f"(v.x * w), "f"(v.y * w), "f"(v.z * w), "f"(v.w * w)
                     : "memory");
    }
}

__global__ void k_zero_out(float* out) {
    if (threadIdx.x == 0 && blockIdx.x == 0) out[0] = 0.0f;
}

// -------- fused final loss: one warp per batch element --------
__global__ void k_loss(const float* __restrict__ emb,
                       const int* __restrict__ user,
                       const int* __restrict__ pos,
                       const int* __restrict__ neg,
                       float* __restrict__ out) {
    int w = (blockIdx.x * blockDim.x + threadIdx.x) >> 5;
    int lane = threadIdx.x & 31;
    if (w >= BATCH) return;

    int ui = user[w], pi = pos[w], ni = neg[w];

    const float2* E = (const float2*)emb;
    const float2* A = (const float2*)g_XA;
    const float2* B = (const float2*)g_XB;
    const float2* C = (const float2*)g_XC;

    size_t uo = (size_t)ui * 32 + lane;
    size_t po = (size_t)pi * 32 + lane;
    size_t no = (size_t)ni * 32 + lane;

    float2 eu = __ldg(E + uo), ep = __ldg(E + po), en = __ldg(E + no);
    float2 au = __ldg(A + uo), bu = __ldg(B + uo), cu = __ldg(C + uo);
    float2 ap = __ldg(A + po), bp = __ldg(B + po), cp = __ldg(C + po);
    float2 an = __ldg(A + no), bn = __ldg(B + no), cn = __ldg(C + no);

    float ux = eu.x + au.x + bu.x + cu.x, uy = eu.y + au.y + bu.y + cu.y;
    float px = ep.x + ap.x + bp.x + cp.x, py = ep.y + ap.y + bp.y + cp.y;
    float nx = en.x + an.x + bn.x + cn.x, ny = en.y + an.y + bn.y + cn.y;

    float pd = ux * px + uy * py;
    float nd = ux * nx + uy * ny;
    float sq = eu.x * eu.x + eu.y * eu.y
             + ep.x * ep.x + ep.y * ep.y
             + en.x * en.x + en.y * en.y;

#pragma unroll
    for (int o = 16; o; o >>= 1) {
        pd += __shfl_xor_sync(0xffffffffu, pd, o);
        nd += __shfl_xor_sync(0xffffffffu, nd, o);
        sq += __shfl_xor_sync(0xffffffffu, sq, o);
    }
    if (lane == 0) {
        float z = (nd - pd) * 0.0625f;                       // /16 for mean^2
        float sp = fmaxf(z, 0.f) + log1pf(expf(-fabsf(z)));  // softplus(neg-pos)
        atomicAdd(out, (sp + 5e-5f * sq) * (1.0f / BATCH));  // + L2_REG*0.5/BATCH
    }
}

extern "C" void kernel_launch(void* const* d_in, const int* in_sizes, int n_in,
                              void* d_out, int out_size) {
    const float* emb  = (const float*)d_in[0];
    const int*   edge = (const int*)d_in[1];
    const int*   src  = edge;
    const int*   dst  = edge + N_EDGES;
    const int*   user = (const int*)d_in[2];
    const int*   pos  = (const int*)d_in[3];
    const int*   neg  = (const int*)d_in[4];
    float*       out  = (float*)d_out;

    static cudaStream_t s1 = nullptr, s2 = nullptr;
    static cudaEvent_t evInit, evMark, evA, evB, evDinv, evZ;
    if (!s1) {
        cudaStreamCreateWithFlags(&s1, cudaStreamNonBlocking);
        cudaStreamCreateWithFlags(&s2, cudaStreamNonBlocking);
        cudaEventCreateWithFlags(&evInit, cudaEventDisableTiming);
        cudaEventCreateWithFlags(&evMark, cudaEventDisableTiming);
        cudaEventCreateWithFlags(&evA,    cudaEventDisableTiming);
        cudaEventCreateWithFlags(&evB,    cudaEventDisableTiming);
        cudaEventCreateWithFlags(&evDinv, cudaEventDisableTiming);
        cudaEventCreateWithFlags(&evZ,    cudaEventDisableTiming);
    }

    const int T = 256;
    const int G_NODES = (N_NODES + T - 1) / T;
    const int G_EDGES = (N_EDGES + T - 1) / T;
    const int G_MARK  = (9 * BATCH + T - 1) / T;
    const int G_PROP  = 2048;
    const int G_ZERO  = 1024;

    // origin stream: the serial critical chain (init -> mark -> compact x3)
    k_init<<<G_NODES, T>>>();
    cudaEventRecord(evInit, 0);
    k_mark_batch<<<G_MARK, T>>>(user, pos, neg);
    cudaEventRecord(evMark, 0);
    k_compact<<<G_EDGES, T>>>(src, dst, 2, 1, 1);   // L3 edges -> list2; mark fb1 (+nl1)
    cudaEventRecord(evA, 0);
    k_compact<<<G_EDGES, T>>>(src, dst, 1, 0, 1);   // L2 edges -> list1; mark fb0 (+nl0)
    cudaEventRecord(evB, 0);
    k_compact<<<G_EDGES, T>>>(src, dst, 0, 0, 0);   // L1 edges -> list0

    // side chain (s1): deg -> dinv, needed only by the props; starts after init
    cudaStreamWaitEvent(s1, evInit, 0);
    k_deg<<<G_EDGES, T, 0, s1>>>(dst);
    k_dinv<<<G_NODES, T, 0, s1>>>();
    cudaEventRecord(evDinv, s1);

    // side chain (s2): joins capture via event-wait BEFORE any launch
    cudaStreamWaitEvent(s2, evMark, 0);
    k_zero_out<<<1, 1, 0, s2>>>(out);
    k_zero_list<<<G_ZERO, T, 0, s2>>>(3, 2);        // XC over nl2 (final at mark)
    cudaStreamWaitEvent(s2, evA, 0);
    k_zero_list<<<G_ZERO, T, 0, s2>>>(2, 1);        // XB over nl1 (final at compactA)
    cudaStreamWaitEvent(s2, evB, 0);
    k_zero_list<<<G_ZERO, T, 0, s2>>>(1, 0);        // XA over nl0 (final at compactB)
    cudaEventRecord(evZ, s2);

    // join side chains onto origin before the props
    cudaStreamWaitEvent(0, evDinv, 0);
    cudaStreamWaitEvent(0, evZ, 0);

    // props (weights from dinv on the fly)
    k_prop_list<<<G_PROP, T>>>(emb, 0, 1, 0);       // emb -> XA over list0
    k_prop_list<<<G_PROP, T>>>(emb, 1, 2, 1);       // XA  -> XB over list1
    k_prop_list<<<G_PROP, T>>>(emb, 2, 3, 2);       // XB  -> XC over list2

    // fused loss (out zeroed on s2, ordered via evZ)
    k_loss<<<BATCH / 8, T>>>(emb, user, pos, neg, out);
}

// round 11
// speedup vs baseline: 2.1324x; 1.4474x over previous
#include <cuda_runtime.h>
#include <cstdint>
#include <cstddef>

#define N_USERS   100000
#define N_NODES   500000
#define DIM       64
#define N_EDGES   2000000
#define BATCH     4096
#define NWORDS    ((N_NODES + 31) / 32)    // 15625 words per bitmask

// -------- device scratch (static, allocation-free) --------
// NOTE: never touch these symbols from host code (GB300 ATS would silently
// route through the host shadow at 200GB/s). All access via device selectors.
__device__ float    g_XA[(size_t)N_NODES * DIM];
__device__ float    g_XB[(size_t)N_NODES * DIM];
__device__ float    g_XC[(size_t)N_NODES * DIM];
__device__ float    g_dinv[N_NODES];
__device__ unsigned g_deg[N_NODES];
__device__ unsigned g_fb[3][NWORDS];       // needed-node bitmasks (L2-resident)
__device__ int      g_nl[3][N_NODES];      // compact node lists
__device__ int      g_ncnt[3];
__device__ int2     g_le[3][N_EDGES];      // compact edge lists (src,dst)
__device__ int      g_ecnt[3];

__device__ __forceinline__ float* xbuf(int sel) {
    return sel == 1 ? g_XA : (sel == 2 ? g_XB : g_XC);
}

// -------- init counters + flag bitmasks --------
__global__ void k_init() {
    int i = blockIdx.x * blockDim.x + threadIdx.x;
    if (i < N_NODES) g_deg[i] = 0u;
    if (i < NWORDS) { g_fb[0][i] = 0u; g_fb[1][i] = 0u; g_fb[2][i] = 0u; }
    if (i < 3) { g_ncnt[i] = 0; g_ecnt[i] = 0; }
}

__global__ void k_deg(const int* __restrict__ dst) {
    int e = blockIdx.x * blockDim.x + threadIdx.x;
    if (e < N_EDGES) atomicAdd(&g_deg[dst[e]], 1u);
}

__global__ void k_dinv() {
    int i = blockIdx.x * blockDim.x + threadIdx.x;
    if (i < N_NODES) {
        unsigned d = g_deg[i];
        g_dinv[i] = d ? rsqrtf((float)d) : 0.0f;
    }
}

// warp-aggregated list append (single item): slot valid where pred
__device__ __forceinline__ int wagg_append(int* counter, bool pred) {
    unsigned mask = __ballot_sync(0xffffffffu, pred);
    if (!pred) return -1;
    int lane   = threadIdx.x & 31;
    int leader = __ffs(mask) - 1;
    int rank   = __popc(mask & ((1u << lane) - 1));
    int base = 0;
    if (lane == leader) base = atomicAdd(counter, __popc(mask));
    base = __shfl_sync(mask, base, leader);
    return base + rank;
}

// warp-scan multi-append: each lane contributes cnt items; returns this lane's
// base slot. ONE atomic per warp. All lanes must participate.
__device__ __forceinline__ int wscan_append(int* counter, int cnt) {
    int lane = threadIdx.x & 31;
    int incl = cnt;
#pragma unroll
    for (int o = 1; o < 32; o <<= 1) {
        int v = __shfl_up_sync(0xffffffffu, incl, o);
        if (lane >= o) incl += v;
    }
    int total = __shfl_sync(0xffffffffu, incl, 31);
    int base = 0;
    if (lane == 31 && total) base = atomicAdd(counter, total);
    base = __shfl_sync(0xffffffffu, base, 31);
    return base + incl - cnt;    // exclusive offset
}

// set bit idx in mask L; true if newly set (dedup)
__device__ __forceinline__ bool mark_node(int L, int idx) {
    unsigned bit = 1u << (idx & 31);
    unsigned old = atomicOr(&g_fb[L][idx >> 5], bit);
    return (old & bit) == 0u;
}

__device__ __forceinline__ bool test_node(int L, int idx) {
    return (g_fb[L][idx >> 5] >> (idx & 31)) & 1u;
}

// mark batch nodes in all 3 bitmasks + node lists; one (layer, slot) per thread
__global__ void k_mark_batch(const int* __restrict__ u,
                             const int* __restrict__ p,
                             const int* __restrict__ n) {
    int t = blockIdx.x * blockDim.x + threadIdx.x;
    bool act = (t < 9 * BATCH);
    int L = 0, idx = 0;
    if (act) {
        L = t / (3 * BATCH);
        int r = t - L * (3 * BATCH);
        idx = (r < BATCH) ? u[r]
            : (r < 2 * BATCH) ? p[r - BATCH]
                              : n[r - 2 * BATCH];
        act = mark_node(L, idx);
    }
#pragma unroll
    for (int LL = 0; LL < 3; LL++) {
        bool pred = act && (L == LL);
        int slot = wagg_append(&g_ncnt[LL], pred);
        if (pred) g_nl[LL][slot] = idx;
    }
}

// compaction, 4 edges/thread, warp-scan appends (1 atomic per warp per list):
// gate on bitmask[gate], append passing edges to list[gate]; optionally mark
// sources one layer earlier (+node list).
__global__ void k_compact4s(const int* __restrict__ src, const int* __restrict__ dst,
                            int gate, int prev, int has_prev) {
    int t = blockIdx.x * blockDim.x + threadIdx.x;
    bool inb = (t < N_EDGES / 4);
    int4 d4 = make_int4(0, 0, 0, 0);
    if (inb) d4 = __ldg((const int4*)dst + t);
    int dd[4] = {d4.x, d4.y, d4.z, d4.w};
    bool p[4];
    int cnt = 0;
#pragma unroll
    for (int i = 0; i < 4; i++) {
        p[i] = inb && test_node(gate, dd[i]);
        cnt += p[i];
    }
    int4 s4 = make_int4(0, 0, 0, 0);
    if (cnt) s4 = __ldg((const int4*)src + t);
    int ss[4] = {s4.x, s4.y, s4.z, s4.w};

    int off = wscan_append(&g_ecnt[gate], cnt);
#pragma unroll
    for (int i = 0; i < 4; i++)
        if (p[i]) g_le[gate][off++] = make_int2(ss[i], dd[i]);

    if (has_prev) {
        bool nw[4];
        int ncnt = 0;
#pragma unroll
        for (int i = 0; i < 4; i++) {          // independent atomicOr ops, MLP=4
            nw[i] = p[i] && mark_node(prev, ss[i]);
            ncnt += nw[i];
        }
        int noff = wscan_append(&g_ncnt[prev], ncnt);
#pragma unroll
        for (int i = 0; i < 4; i++)
            if (nw[i]) g_nl[prev][noff++] = ss[i];
    }
}

// zero exactly the rows in node list lsel of buffer xsel (grid-stride)
__global__ void k_zero_list(int xsel, int lsel) {
    int n16 = g_ncnt[lsel] * 16;
    float4* y = (float4*)xbuf(xsel);
    int stride = gridDim.x * blockDim.x;
    for (int t = blockIdx.x * blockDim.x + threadIdx.x; t < n16; t += stride) {
        int node = g_nl[lsel][t >> 4];
        y[(size_t)node * 16 + (t & 15)] = make_float4(0.f, 0.f, 0.f, 0.f);
    }
}

// propagation over compact edge list: 16 threads/edge, grid-stride.
// weight computed on the fly from L2-resident dinv (broadcast across lanes).
__global__ void k_prop_list(const float* __restrict__ emb, int xsel, int ysel, int lsel) {
    int m = g_ecnt[lsel] * 16;
    const float* x = (xsel == 0) ? emb : xbuf(xsel);
    float*       y = xbuf(ysel);
    int stride = gridDim.x * blockDim.x;
    for (int t = blockIdx.x * blockDim.x + threadIdx.x; t < m; t += stride) {
        int e = t >> 4, lane = t & 15;
        int2  sd = __ldg(&g_le[lsel][e]);
        float w = __ldg(g_dinv + sd.x) * __ldg(g_dinv + sd.y);
        float4 v = __ldg((const float4*)x + (size_t)sd.x * 16 + lane);
        float4* a = (float4*)y + (size_t)sd.y * 16 + lane;
        asm volatile("red.global.add.v4.f32 [%0], {%1, %2, %3, %4};"
                     :: "l"(a), "f"(v.x * w), "f"(v.y * w), "f"(v.z * w), "f"(v.w * w)
                     : "memory");
    }
}

__global__ void k_zero_out(float* out) {
    if (threadIdx.x == 0 && blockIdx.x == 0) out[0] = 0.0f;
}

// -------- fused final loss: one warp per batch element --------
__global__ void k_loss(const float* __restrict__ emb,
                       const int* __restrict__ user,
                       const int* __restrict__ pos,
                       const int* __restrict__ neg,
                       float* __restrict__ out) {
    int w = (blockIdx.x * blockDim.x + threadIdx.x) >> 5;
    int lane = threadIdx.x & 31;
    if (w >= BATCH) return;

    int ui = user[w], pi = pos[w], ni = neg[w];

    const float2* E = (const float2*)emb;
    const float2* A = (const float2*)g_XA;
    const float2* B = (const float2*)g_XB;
    const float2* C = (const float2*)g_XC;

    size_t uo = (size_t)ui * 32 + lane;
    size_t po = (size_t)pi * 32 + lane;
    size_t no = (size_t)ni * 32 + lane;

    float2 eu = __ldg(E + uo), ep = __ldg(E + po), en = __ldg(E + no);
    float2 au = __ldg(A + uo), bu = __ldg(B + uo), cu = __ldg(C + uo);
    float2 ap = __ldg(A + po), bp = __ldg(B + po), cp = __ldg(C + po);
    float2 an = __ldg(A + no), bn = __ldg(B + no), cn = __ldg(C + no);

    float ux = eu.x + au.x + bu.x + cu.x, uy = eu.y + au.y + bu.y + cu.y;
    float px = ep.x + ap.x + bp.x + cp.x, py = ep.y + ap.y + bp.y + cp.y;
    float nx = en.x + an.x + bn.x + cn.x, ny = en.y + an.y + bn.y + cn.y;

    float pd = ux * px + uy * py;
    float nd = ux * nx + uy * ny;
    float sq = eu.x * eu.x + eu.y * eu.y
             + ep.x * ep.x + ep.y * ep.y
             + en.x * en.x + en.y * en.y;

#pragma unroll
    for (int o = 16; o; o >>= 1) {
        pd += __shfl_xor_sync(0xffffffffu, pd, o);
        nd += __shfl_xor_sync(0xffffffffu, nd, o);
        sq += __shfl_xor_sync(0xffffffffu, sq, o);
    }
    if (lane == 0) {
        float z = (nd - pd) * 0.0625f;                       // /16 for mean^2
        float sp = fmaxf(z, 0.f) + log1pf(expf(-fabsf(z)));  // softplus(neg-pos)
        atomicAdd(out, (sp + 5e-5f * sq) * (1.0f / BATCH));  // + L2_REG*0.5/BATCH
    }
}

extern "C" void kernel_launch(void* const* d_in, const int* in_sizes, int n_in,
                              void* d_out, int out_size) {
    const float* emb  = (const float*)d_in[0];
    const int*   edge = (const int*)d_in[1];
    const int*   src  = edge;
    const int*   dst  = edge + N_EDGES;
    const int*   user = (const int*)d_in[2];
    const int*   pos  = (const int*)d_in[3];
    const int*   neg  = (const int*)d_in[4];
    float*       out  = (float*)d_out;

    static cudaStream_t s1 = nullptr, s2 = nullptr;
    static cudaEvent_t evInit, evMark, evA, evB, evDinv, evZ;
    if (!s1) {
        cudaStreamCreateWithFlags(&s1, cudaStreamNonBlocking);
        cudaStreamCreateWithFlags(&s2, cudaStreamNonBlocking);
        cudaEventCreateWithFlags(&evInit, cudaEventDisableTiming);
        cudaEventCreateWithFlags(&evMark, cudaEventDisableTiming);
        cudaEventCreateWithFlags(&evA,    cudaEventDisableTiming);
        cudaEventCreateWithFlags(&evB,    cudaEventDisableTiming);
        cudaEventCreateWithFlags(&evDinv, cudaEventDisableTiming);
        cudaEventCreateWithFlags(&evZ,    cudaEventDisableTiming);
    }

    const int T = 256;
    const int G_NODES = (N_NODES + T - 1) / T;
    const int G_EDGES = (N_EDGES + T - 1) / T;
    const int G_CMP   = (N_EDGES / 4 + T - 1) / T;   // 1954
    const int G_MARK  = (9 * BATCH + T - 1) / T;
    const int G_PROP  = 2048;
    const int G_ZERO  = 1024;

    // origin stream: the serial critical chain (init -> mark -> compact x3)
    k_init<<<G_NODES, T>>>();
    cudaEventRecord(evInit, 0);
    k_mark_batch<<<G_MARK, T>>>(user, pos, neg);
    cudaEventRecord(evMark, 0);
    k_compact4s<<<G_CMP, T>>>(src, dst, 2, 1, 1);   // L3 edges -> list2; mark fb1 (+nl1)
    cudaEventRecord(evA, 0);
    k_compact4s<<<G_CMP, T>>>(src, dst, 1, 0, 1);   // L2 edges -> list1; mark fb0 (+nl0)
    cudaEventRecord(evB, 0);
    k_compact4s<<<G_CMP, T>>>(src, dst, 0, 0, 0);   // L1 edges -> list0

    // side chain (s1): deg -> dinv, needed only by the props; starts after init
    cudaStreamWaitEvent(s1, evInit, 0);
    k_deg<<<G_EDGES, T, 0, s1>>>(dst);
    k_dinv<<<G_NODES, T, 0, s1>>>();
    cudaEventRecord(evDinv, s1);

    // side chain (s2): joins capture via event-wait BEFORE any launch
    cudaStreamWaitEvent(s2, evMark, 0);
    k_zero_out<<<1, 1, 0, s2>>>(out);
    k_zero_list<<<G_ZERO, T, 0, s2>>>(3, 2);        // XC over nl2 (final at mark)
    cudaStreamWaitEvent(s2, evA, 0);
    k_zero_list<<<G_ZERO, T, 0, s2>>>(2, 1);        // XB over nl1 (final at compactA)
    cudaStreamWaitEvent(s2, evB, 0);
    k_zero_list<<<G_ZERO, T, 0, s2>>>(1, 0);        // XA over nl0 (final at compactB)
    cudaEventRecord(evZ, s2);

    // join side chains onto origin before the props
    cudaStreamWaitEvent(0, evDinv, 0);
    cudaStreamWaitEvent(0, evZ, 0);

    // props (weights from dinv on the fly)
    k_prop_list<<<G_PROP, T>>>(emb, 0, 1, 0);       // emb -> XA over list0
    k_prop_list<<<G_PROP, T>>>(emb, 1, 2, 1);       // XA  -> XB over list1
    k_prop_list<<<G_PROP, T>>>(emb, 2, 3, 2);       // XB  -> XC over list2

    // fused loss (out zeroed on s2, ordered via evZ)
    k_loss<<<BATCH / 8, T>>>(emb, user, pos, neg, out);
}

// round 12
// speedup vs baseline: 2.1878x; 1.0260x over previous
#include <cuda_runtime.h>
#include <cstdint>
#include <cstddef>

#define N_USERS   100000
#define N_NODES   500000
#define DIM       64
#define N_EDGES   2000000
#define BATCH     4096
#define NWORDS    ((N_NODES + 31) / 32)    // 15625 words per bitmask

// -------- device scratch (static, allocation-free) --------
// NOTE: never touch these symbols from host code (GB300 ATS would silently
// route through the host shadow at 200GB/s). All access via device selectors.
__device__ float    g_XA[(size_t)N_NODES * DIM];
__device__ float    g_XB[(size_t)N_NODES * DIM];
__device__ float    g_XC[(size_t)N_NODES * DIM];
__device__ float    g_dinv[N_NODES];
__device__ unsigned g_deg[N_NODES];
__device__ unsigned g_fb[3][NWORDS];       // needed-node bitmasks (L2-resident)
__device__ int      g_nl[3][N_NODES];      // compact node lists
__device__ int      g_ncnt[3];
__device__ int2     g_le[3][N_EDGES];      // compact edge lists (src,dst)
__device__ int      g_ecnt[3];

__device__ __forceinline__ float* xbuf(int sel) {
    return sel == 1 ? g_XA : (sel == 2 ? g_XB : g_XC);
}

// -------- init counters + flag bitmasks --------
__global__ void k_init() {
    int i = blockIdx.x * blockDim.x + threadIdx.x;
    if (i < N_NODES) g_deg[i] = 0u;
    if (i < NWORDS) { g_fb[0][i] = 0u; g_fb[1][i] = 0u; g_fb[2][i] = 0u; }
    if (i < 3) { g_ncnt[i] = 0; g_ecnt[i] = 0; }
}

__global__ void k_deg(const int* __restrict__ dst) {
    int e = blockIdx.x * blockDim.x + threadIdx.x;
    if (e < N_EDGES) atomicAdd(&g_deg[dst[e]], 1u);
}

__global__ void k_dinv() {
    int i = blockIdx.x * blockDim.x + threadIdx.x;
    if (i < N_NODES) {
        unsigned d = g_deg[i];
        g_dinv[i] = d ? rsqrtf((float)d) : 0.0f;
    }
}

// warp-aggregated single-item append
__device__ __forceinline__ int wagg_append(int* counter, bool pred) {
    unsigned mask = __ballot_sync(0xffffffffu, pred);
    if (!pred) return -1;
    int lane   = threadIdx.x & 31;
    int leader = __ffs(mask) - 1;
    int rank   = __popc(mask & ((1u << lane) - 1));
    int base = 0;
    if (lane == leader) base = atomicAdd(counter, __popc(mask));
    base = __shfl_sync(mask, base, leader);
    return base + rank;
}

// warp-scan multi-append: each lane contributes cnt items; returns this lane's
// base slot. ONE atomic per warp. All lanes must participate.
__device__ __forceinline__ int wscan_append(int* counter, int cnt) {
    int lane = threadIdx.x & 31;
    int incl = cnt;
#pragma unroll
    for (int o = 1; o < 32; o <<= 1) {
        int v = __shfl_up_sync(0xffffffffu, incl, o);
        if (lane >= o) incl += v;
    }
    int total = __shfl_sync(0xffffffffu, incl, 31);
    int base = 0;
    if (lane == 31 && total) base = atomicAdd(counter, total);
    base = __shfl_sync(0xffffffffu, base, 31);
    return base + incl - cnt;    // exclusive offset
}

// set bit idx in mask L; true if newly set (dedup)
__device__ __forceinline__ bool mark_node(int L, int idx) {
    unsigned bit = 1u << (idx & 31);
    unsigned old = atomicOr(&g_fb[L][idx >> 5], bit);
    return (old & bit) == 0u;
}

__device__ __forceinline__ bool test_node(int L, int idx) {
    return (g_fb[L][idx >> 5] >> (idx & 31)) & 1u;
}

// mark batch nodes in all 3 bitmasks + node lists; one (layer, slot) per thread
__global__ void k_mark_batch(const int* __restrict__ u,
                             const int* __restrict__ p,
                             const int* __restrict__ n) {
    int t = blockIdx.x * blockDim.x + threadIdx.x;
    bool act = (t < 9 * BATCH);
    int L = 0, idx = 0;
    if (act) {
        L = t / (3 * BATCH);
        int r = t - L * (3 * BATCH);
        idx = (r < BATCH) ? u[r]
            : (r < 2 * BATCH) ? p[r - BATCH]
                              : n[r - 2 * BATCH];
        act = mark_node(L, idx);
    }
#pragma unroll
    for (int LL = 0; LL < 3; LL++) {
        bool pred = act && (L == LL);
        int slot = wagg_append(&g_ncnt[LL], pred);
        if (pred) g_nl[LL][slot] = idx;
    }
}

// compaction, 8 edges/thread, warp-scan appends (1 atomic per warp per list):
// pass condition: f[gate][dst] && (excl < 0 || !f[excl][dst]).
// optionally mark sources one layer earlier (+node list).
__global__ void k_compact8s(const int* __restrict__ src, const int* __restrict__ dst,
                            int gate, int excl, int prev, int has_prev) {
    int t = blockIdx.x * blockDim.x + threadIdx.x;
    bool inb = (t < N_EDGES / 8);
    int4 dA = make_int4(0,0,0,0), dB = make_int4(0,0,0,0);
    if (inb) {
        dA = __ldg((const int4*)dst + 2 * t);
        dB = __ldg((const int4*)dst + 2 * t + 1);
    }
    int dd[8] = {dA.x, dA.y, dA.z, dA.w, dB.x, dB.y, dB.z, dB.w};
    bool p[8];
    int cnt = 0;
#pragma unroll
    for (int i = 0; i < 8; i++) {
        p[i] = inb && test_node(gate, dd[i]);
        if (excl >= 0 && p[i]) p[i] = !test_node(excl, dd[i]);
        cnt += p[i];
    }
    int4 sA = make_int4(0,0,0,0), sB = make_int4(0,0,0,0);
    if (cnt) {
        sA = __ldg((const int4*)src + 2 * t);
        sB = __ldg((const int4*)src + 2 * t + 1);
    }
    int ss[8] = {sA.x, sA.y, sA.z, sA.w, sB.x, sB.y, sB.z, sB.w};

    int off = wscan_append(&g_ecnt[gate], cnt);
#pragma unroll
    for (int i = 0; i < 8; i++)
        if (p[i]) g_le[gate][off++] = make_int2(ss[i], dd[i]);

    if (has_prev) {
        bool nw[8];
        int ncnt = 0;
#pragma unroll
        for (int i = 0; i < 8; i++) {          // independent atomicOr ops, MLP=8
            nw[i] = p[i] && mark_node(prev, ss[i]);
            ncnt += nw[i];
        }
        int noff = wscan_append(&g_ncnt[prev], ncnt);
#pragma unroll
        for (int i = 0; i < 8; i++)
            if (nw[i]) g_nl[prev][noff++] = ss[i];
    }
}

// zero exactly the rows in node list lsel of buffer xsel (grid-stride)
__global__ void k_zero_list(int xsel, int lsel) {
    int n16 = g_ncnt[lsel] * 16;
    float4* y = (float4*)xbuf(xsel);
    int stride = gridDim.x * blockDim.x;
    for (int t = blockIdx.x * blockDim.x + threadIdx.x; t < n16; t += stride) {
        int node = g_nl[lsel][t >> 4];
        y[(size_t)node * 16 + (t & 15)] = make_float4(0.f, 0.f, 0.f, 0.f);
    }
}

// propagation over compact edge list: 16 threads/edge, grid-stride.
// weight computed on the fly from L2-resident dinv (broadcast across lanes).
__global__ void k_prop_list(const float* __restrict__ emb, int xsel, int ysel, int lsel) {
    int m = g_ecnt[lsel] * 16;
    const float* x = (xsel == 0) ? emb : xbuf(xsel);
    float*       y = xbuf(ysel);
    int stride = gridDim.x * blockDim.x;
    for (int t = blockIdx.x * blockDim.x + threadIdx.x; t < m; t += stride) {
        int e = t >> 4, lane = t & 15;
        int2  sd = __ldg(&g_le[lsel][e]);
        float w = __ldg(g_dinv + sd.x) * __ldg(g_dinv + sd.y);
        float4 v = __ldg((const float4*)x + (size_t)sd.x * 16 + lane);
        float4* a = (float4*)y + (size_t)sd.y * 16 + lane;
        asm volatile("red.global.add.v4.f32 [%0], {%1, %2, %3, %4};"
                     :: "l"(a), "f"(v.x * w), "f"(v.y * w), "f"(v.z * w), "f"(v.w * w)
                     : "memory");
    }
}

__global__ void k_zero_out(float* out) {
    if (threadIdx.x == 0 && blockIdx.x == 0) out[0] = 0.0f;
}

// -------- fused final loss: one warp per batch element --------
__global__ void k_loss(const float* __restrict__ emb,
                       const int* __restrict__ user,
                       const int* __restrict__ pos,
                       const int* __restrict__ neg,
                       float* __restrict__ out) {
    int w = (blockIdx.x * blockDim.x + threadIdx.x) >> 5;
    int lane = threadIdx.x & 31;
    if (w >= BATCH) return;

    int ui = user[w], pi = pos[w], ni = neg[w];

    const float2* E = (const float2*)emb;
    const float2* A = (const float2*)g_XA;
    const float2* B = (const float2*)g_XB;
    const float2* C = (const float2*)g_XC;

    size_t uo = (size_t)ui * 32 + lane;
    size_t po = (size_t)pi * 32 + lane;
    size_t no = (size_t)ni * 32 + lane;

    float2 eu = __ldg(E + uo), ep = __ldg(E + po), en = __ldg(E + no);
    float2 au = __ldg(A + uo), bu = __ldg(B + uo), cu = __ldg(C + uo);
    float2 ap = __ldg(A + po), bp = __ldg(B + po), cp = __ldg(C + po);
    float2 an = __ldg(A + no), bn = __ldg(B + no), cn = __ldg(C + no);

    float ux = eu.x + au.x + bu.x + cu.x, uy = eu.y + au.y + bu.y + cu.y;
    float px = ep.x + ap.x + bp.x + cp.x, py = ep.y + ap.y + bp.y + cp.y;
    float nx = en.x + an.x + bn.x + cn.x, ny = en.y + an.y + bn.y + cn.y;

    float pd = ux * px + uy * py;
    float nd = ux * nx + uy * ny;
    float sq = eu.x * eu.x + eu.y * eu.y
             + ep.x * ep.x + ep.y * ep.y
             + en.x * en.x + en.y * en.y;

#pragma unroll
    for (int o = 16; o; o >>= 1) {
        pd += __shfl_xor_sync(0xffffffffu, pd, o);
        nd += __shfl_xor_sync(0xffffffffu, nd, o);
        sq += __shfl_xor_sync(0xffffffffu, sq, o);
    }
    if (lane == 0) {
        float z = (nd - pd) * 0.0625f;                       // /16 for mean^2
        float sp = fmaxf(z, 0.f) + log1pf(expf(-fabsf(z)));  // softplus(neg-pos)
        atomicAdd(out, (sp + 5e-5f * sq) * (1.0f / BATCH));  // + L2_REG*0.5/BATCH
    }
}

extern "C" void kernel_launch(void* const* d_in, const int* in_sizes, int n_in,
                              void* d_out, int out_size) {
    const float* emb  = (const float*)d_in[0];
    const int*   edge = (const int*)d_in[1];
    const int*   src  = edge;
    const int*   dst  = edge + N_EDGES;
    const int*   user = (const int*)d_in[2];
    const int*   pos  = (const int*)d_in[3];
    const int*   neg  = (const int*)d_in[4];
    float*       out  = (float*)d_out;

    static cudaStream_t s1 = nullptr, s2 = nullptr;
    static cudaEvent_t evInit, evMark, evA, evB, evZ, evP1;
    if (!s1) {
        cudaStreamCreateWithFlags(&s1, cudaStreamNonBlocking);
        cudaStreamCreateWithFlags(&s2, cudaStreamNonBlocking);
        cudaEventCreateWithFlags(&evInit, cudaEventDisableTiming);
        cudaEventCreateWithFlags(&evMark, cudaEventDisableTiming);
        cudaEventCreateWithFlags(&evA,    cudaEventDisableTiming);
        cudaEventCreateWithFlags(&evB,    cudaEventDisableTiming);
        cudaEventCreateWithFlags(&evZ,    cudaEventDisableTiming);
        cudaEventCreateWithFlags(&evP1,   cudaEventDisableTiming);
    }

    const int T = 256;
    const int G_NODES = (N_NODES + T - 1) / T;
    const int G_EDGES = (N_EDGES + T - 1) / T;
    const int G_CMP   = (N_EDGES / 8 + T - 1) / T;   // 977
    const int G_MARK  = (9 * BATCH + T - 1) / T;
    const int G_PROP  = 2048;
    const int G_ZERO  = 1024;

    // origin stream: the serial critical chain (init -> mark -> compacts)
    k_init<<<G_NODES, T>>>();
    cudaEventRecord(evInit, 0);
    k_mark_batch<<<G_MARK, T>>>(user, pos, neg);
    cudaEventRecord(evMark, 0);
    k_compact8s<<<G_CMP, T>>>(src, dst, 2, -1, 1, 1); // f2 edges -> list2; mark fb1 (+nl1)
    cudaEventRecord(evA, 0);
    k_compact8s<<<G_CMP, T>>>(src, dst, 1, -1, 0, 1); // f1 edges -> list1; mark fb0 (+nl0)
    cudaEventRecord(evB, 0);
    // compactC runs CONCURRENTLY with prop1a (below): only f0 && !f1 edges
    k_compact8s<<<G_CMP, T>>>(src, dst, 0, 1, 0, 0);  // -> list0 (~810k edges)

    // side chain (s1): deg -> dinv (needed by props); then prop1a over list1
    // (list1 ⊆ list0-edge-set; its dsts are f1 ⊆ f0 rows of XA, zeroed on s2)
    cudaStreamWaitEvent(s1, evInit, 0);
    k_deg<<<G_EDGES, T, 0, s1>>>(dst);
    k_dinv<<<G_NODES, T, 0, s1>>>();

    // side chain (s2): joins capture via event-wait BEFORE any launch
    cudaStreamWaitEvent(s2, evMark, 0);
    k_zero_out<<<1, 1, 0, s2>>>(out);
    k_zero_list<<<G_ZERO, T, 0, s2>>>(3, 2);        // XC over nl2 (final at mark)
    cudaStreamWaitEvent(s2, evA, 0);
    k_zero_list<<<G_ZERO, T, 0, s2>>>(2, 1);        // XB over nl1 (final at compactA)
    cudaStreamWaitEvent(s2, evB, 0);
    k_zero_list<<<G_ZERO, T, 0, s2>>>(1, 0);        // XA over nl0 (final at compactB)
    cudaEventRecord(evZ, s2);

    // prop1a on s1: emb -> XA over list1 edges, overlapped with compactC
    cudaStreamWaitEvent(s1, evZ, 0);                // XA zeroed (implies evB done)
    k_prop_list<<<G_PROP, T, 0, s1>>>(emb, 0, 1, 1);
    cudaEventRecord(evP1, s1);

    // join everything onto origin before the remaining props
    cudaStreamWaitEvent(0, evZ, 0);
    cudaStreamWaitEvent(0, evP1, 0);

    // prop1b: remaining layer-1 edges (f0 && !f1) -> XA
    k_prop_list<<<G_PROP, T>>>(emb, 0, 1, 0);
    // layers 2/3 over lists 1/2
    k_prop_list<<<G_PROP, T>>>(emb, 1, 2, 1);       // XA -> XB over list1
    k_prop_list<<<G_PROP, T>>>(emb, 2, 3, 2);       // XB -> XC over list2

    // fused loss (out zeroed on s2, ordered via evZ)
    k_loss<<<BATCH / 8, T>>>(emb, user, pos, neg, out);
}

// round 13
// speedup vs baseline: 2.2950x; 1.0490x over previous
#include <cuda_runtime.h>
#include <cuda_bf16.h>
#include <cstdint>
#include <cstddef>

#define N_USERS   100000
#define N_NODES   500000
#define DIM       64
#define N_EDGES   2000000
#define BATCH     4096
#define NWORDS    ((N_NODES + 31) / 32)

// -------- device scratch (static, allocation-free) --------
// NOTE: never touch these symbols from host code (GB300 ATS would silently
// route through the host shadow at 200GB/s). All access via device selectors.
__device__ __nv_bfloat16 g_EB[(size_t)N_NODES * DIM];  // bf16 copy of emb
__device__ __nv_bfloat16 g_XA[(size_t)N_NODES * DIM];  // bf16 layer buffers
__device__ __nv_bfloat16 g_XB[(size_t)N_NODES * DIM];
__device__ __nv_bfloat16 g_XC[(size_t)N_NODES * DIM];
__device__ float    g_dinv[N_NODES];
__device__ unsigned g_deg[N_NODES];
__device__ unsigned g_fb[3][NWORDS];       // needed-node bitmasks (L2-resident)
__device__ int      g_nl[3][N_NODES];      // compact node lists
__device__ int      g_ncnt[3];
__device__ int2     g_le[3][N_EDGES];      // compact edge lists (src,dst)
__device__ int      g_ecnt[3];

__device__ __forceinline__ __nv_bfloat16* xbuf(int sel) {
    return sel == 0 ? g_EB : (sel == 1 ? g_XA : (sel == 2 ? g_XB : g_XC));
}

// -------- init counters + flag bitmasks --------
__global__ void k_init() {
    int i = blockIdx.x * blockDim.x + threadIdx.x;
    if (i < N_NODES) g_deg[i] = 0u;
    if (i < NWORDS) { g_fb[0][i] = 0u; g_fb[1][i] = 0u; g_fb[2][i] = 0u; }
    if (i < 3) { g_ncnt[i] = 0; g_ecnt[i] = 0; }
}

__global__ void k_deg(const int* __restrict__ dst) {
    int e = blockIdx.x * blockDim.x + threadIdx.x;
    if (e < N_EDGES) atomicAdd(&g_deg[dst[e]], 1u);
}

__global__ void k_dinv() {
    int i = blockIdx.x * blockDim.x + threadIdx.x;
    if (i < N_NODES) {
        unsigned d = g_deg[i];
        g_dinv[i] = d ? rsqrtf((float)d) : 0.0f;
    }
}

// convert emb (fp32) -> g_EB (bf16); one thread per 8 floats
__global__ void k_conv(const float* __restrict__ emb) {
    int t = blockIdx.x * blockDim.x + threadIdx.x;
    if (t >= N_NODES * (DIM / 8)) return;
    float4 a = __ldg((const float4*)emb + 2 * (size_t)t);
    float4 b = __ldg((const float4*)emb + 2 * (size_t)t + 1);
    __nv_bfloat162 p0 = __float22bfloat162_rn(make_float2(a.x, a.y));
    __nv_bfloat162 p1 = __float22bfloat162_rn(make_float2(a.z, a.w));
    __nv_bfloat162 p2 = __float22bfloat162_rn(make_float2(b.x, b.y));
    __nv_bfloat162 p3 = __float22bfloat162_rn(make_float2(b.z, b.w));
    uint4 o;
    o.x = *(unsigned*)&p0; o.y = *(unsigned*)&p1;
    o.z = *(unsigned*)&p2; o.w = *(unsigned*)&p3;
    ((uint4*)g_EB)[t] = o;
}

// warp-aggregated single-item append
__device__ __forceinline__ int wagg_append(int* counter, bool pred) {
    unsigned mask = __ballot_sync(0xffffffffu, pred);
    if (!pred) return -1;
    int lane   = threadIdx.x & 31;
    int leader = __ffs(mask) - 1;
    int rank   = __popc(mask & ((1u << lane) - 1));
    int base = 0;
    if (lane == leader) base = atomicAdd(counter, __popc(mask));
    base = __shfl_sync(mask, base, leader);
    return base + rank;
}

// warp-scan multi-append: ONE atomic per warp; all lanes participate
__device__ __forceinline__ int wscan_append(int* counter, int cnt) {
    int lane = threadIdx.x & 31;
    int incl = cnt;
#pragma unroll
    for (int o = 1; o < 32; o <<= 1) {
        int v = __shfl_up_sync(0xffffffffu, incl, o);
        if (lane >= o) incl += v;
    }
    int total = __shfl_sync(0xffffffffu, incl, 31);
    int base = 0;
    if (lane == 31 && total) base = atomicAdd(counter, total);
    base = __shfl_sync(0xffffffffu, base, 31);
    return base + incl - cnt;
}

__device__ __forceinline__ bool mark_node(int L, int idx) {
    unsigned bit = 1u << (idx & 31);
    unsigned old = atomicOr(&g_fb[L][idx >> 5], bit);
    return (old & bit) == 0u;
}

__device__ __forceinline__ bool test_node(int L, int idx) {
    return (g_fb[L][idx >> 5] >> (idx & 31)) & 1u;
}

// mark batch nodes in all 3 bitmasks + node lists
__global__ void k_mark_batch(const int* __restrict__ u,
                             const int* __restrict__ p,
                             const int* __restrict__ n) {
    int t = blockIdx.x * blockDim.x + threadIdx.x;
    bool act = (t < 9 * BATCH);
    int L = 0, idx = 0;
    if (act) {
        L = t / (3 * BATCH);
        int r = t - L * (3 * BATCH);
        idx = (r < BATCH) ? u[r]
            : (r < 2 * BATCH) ? p[r - BATCH]
                              : n[r - 2 * BATCH];
        act = mark_node(L, idx);
    }
#pragma unroll
    for (int LL = 0; LL < 3; LL++) {
        bool pred = act && (L == LL);
        int slot = wagg_append(&g_ncnt[LL], pred);
        if (pred) g_nl[LL][slot] = idx;
    }
}

// compaction, 8 edges/thread, warp-scan appends.
// pass: f[gate][dst] && (excl < 0 || !f[excl][dst]); optionally mark prev.
__global__ void k_compact8s(const int* __restrict__ src, const int* __restrict__ dst,
                            int gate, int excl, int prev, int has_prev) {
    int t = blockIdx.x * blockDim.x + threadIdx.x;
    bool inb = (t < N_EDGES / 8);
    int4 dA = make_int4(0,0,0,0), dB = make_int4(0,0,0,0);
    if (inb) {
        dA = __ldg((const int4*)dst + 2 * t);
        dB = __ldg((const int4*)dst + 2 * t + 1);
    }
    int dd[8] = {dA.x, dA.y, dA.z, dA.w, dB.x, dB.y, dB.z, dB.w};
    bool p[8];
    int cnt = 0;
#pragma unroll
    for (int i = 0; i < 8; i++) {
        p[i] = inb && test_node(gate, dd[i]);
        if (excl >= 0 && p[i]) p[i] = !test_node(excl, dd[i]);
        cnt += p[i];
    }
    int4 sA = make_int4(0,0,0,0), sB = make_int4(0,0,0,0);
    if (cnt) {
        sA = __ldg((const int4*)src + 2 * t);
        sB = __ldg((const int4*)src + 2 * t + 1);
    }
    int ss[8] = {sA.x, sA.y, sA.z, sA.w, sB.x, sB.y, sB.z, sB.w};

    int off = wscan_append(&g_ecnt[gate], cnt);
#pragma unroll
    for (int i = 0; i < 8; i++)
        if (p[i]) g_le[gate][off++] = make_int2(ss[i], dd[i]);

    if (has_prev) {
        bool nw[8];
        int ncnt = 0;
#pragma unroll
        for (int i = 0; i < 8; i++) {
            nw[i] = p[i] && mark_node(prev, ss[i]);
            ncnt += nw[i];
        }
        int noff = wscan_append(&g_ncnt[prev], ncnt);
#pragma unroll
        for (int i = 0; i < 8; i++)
            if (nw[i]) g_nl[prev][noff++] = ss[i];
    }
}

// zero rows in node list lsel of bf16 buffer xsel (128B rows = 8 x uint4)
__global__ void k_zero_list(int xsel, int lsel) {
    int n8 = g_ncnt[lsel] * 8;
    uint4* y = (uint4*)xbuf(xsel);
    int stride = gridDim.x * blockDim.x;
    for (int t = blockIdx.x * blockDim.x + threadIdx.x; t < n8; t += stride) {
        int node = g_nl[lsel][t >> 3];
        y[(size_t)node * 8 + (t & 7)] = make_uint4(0u, 0u, 0u, 0u);
    }
}

// bf16 propagation over compact edge list: 8 lanes/edge, grid-stride.
// 16B gather, bf16x2 multiply, red.global.add.noftz.v4.bf16x2 scatter.
__global__ void k_prop_list(int xsel, int ysel, int lsel) {
    int m = g_ecnt[lsel] * 8;
    const uint4* x = (const uint4*)xbuf(xsel);
    uint4*       y = (uint4*)xbuf(ysel);
    int stride = gridDim.x * blockDim.x;
    for (int t = blockIdx.x * blockDim.x + threadIdx.x; t < m; t += stride) {
        int e = t >> 3, lane = t & 7;
        int2  sd = __ldg(&g_le[lsel][e]);
        float w = __ldg(g_dinv + sd.x) * __ldg(g_dinv + sd.y);
        __nv_bfloat162 w2 = __float2bfloat162_rn(w);
        uint4 v = __ldg(x + (size_t)sd.x * 8 + lane);
        __nv_bfloat162 q0 = __hmul2(*(__nv_bfloat162*)&v.x, w2);
        __nv_bfloat162 q1 = __hmul2(*(__nv_bfloat162*)&v.y, w2);
        __nv_bfloat162 q2 = __hmul2(*(__nv_bfloat162*)&v.z, w2);
        __nv_bfloat162 q3 = __hmul2(*(__nv_bfloat162*)&v.w, w2);
        uint4* a = y + (size_t)sd.y * 8 + lane;
        asm volatile("red.global.add.noftz.v4.bf16x2 [%0], {%1, %2, %3, %4};"
                     :: "l"(a), "r"(*(unsigned*)&q0), "r"(*(unsigned*)&q1),
                        "r"(*(unsigned*)&q2), "r"(*(unsigned*)&q3)
                     : "memory");
    }
}

__global__ void k_zero_out(float* out) {
    if (threadIdx.x == 0 && blockIdx.x == 0) out[0] = 0.0f;
}

// -------- fused final loss: one warp per batch element --------
// propagated layers read as bf16 (1 bf16x2 per lane per buffer); ego emb fp32.
__global__ void k_loss(const float* __restrict__ emb,
                       const int* __restrict__ user,
                       const int* __restrict__ pos,
                       const int* __restrict__ neg,
                       float* __restrict__ out) {
    int w = (blockIdx.x * blockDim.x + threadIdx.x) >> 5;
    int lane = threadIdx.x & 31;
    if (w >= BATCH) return;

    int ui = user[w], pi = pos[w], ni = neg[w];

    const float2* E = (const float2*)emb;
    const __nv_bfloat162* A = (const __nv_bfloat162*)g_XA;
    const __nv_bfloat162* B = (const __nv_bfloat162*)g_XB;
    const __nv_bfloat162* C = (const __nv_bfloat162*)g_XC;

    size_t uo = (size_t)ui * 32 + lane;
    size_t po = (size_t)pi * 32 + lane;
    size_t no = (size_t)ni * 32 + lane;

    float2 eu = __ldg(E + uo), ep = __ldg(E + po), en = __ldg(E + no);
    float2 au = __bfloat1622float2(A[uo]), bu = __bfloat1622float2(B[uo]),
           cu = __bfloat1622float2(C[uo]);
    float2 ap = __bfloat1622float2(A[po]), bp = __bfloat1622float2(B[po]),
           cp = __bfloat1622float2(C[po]);
    float2 an = __bfloat1622float2(A[no]), bn = __bfloat1622float2(B[no]),
           cn = __bfloat1622float2(C[no]);

    float ux = eu.x + au.x + bu.x + cu.x, uy = eu.y + au.y + bu.y + cu.y;
    float px = ep.x + ap.x + bp.x + cp.x, py = ep.y + ap.y + bp.y + cp.y;
    float nx = en.x + an.x + bn.x + cn.x, ny = en.y + an.y + bn.y + cn.y;

    float pd = ux * px + uy * py;
    float nd = ux * nx + uy * ny;
    float sq = eu.x * eu.x + eu.y * eu.y
             + ep.x * ep.x + ep.y * ep.y
             + en.x * en.x + en.y * en.y;

#pragma unroll
    for (int o = 16; o; o >>= 1) {
        pd += __shfl_xor_sync(0xffffffffu, pd, o);
        nd += __shfl_xor_sync(0xffffffffu, nd, o);
        sq += __shfl_xor_sync(0xffffffffu, sq, o);
    }
    if (lane == 0) {
        float z = (nd - pd) * 0.0625f;                       // /16 for mean^2
        float sp = fmaxf(z, 0.f) + log1pf(expf(-fabsf(z)));  // softplus(neg-pos)
        atomicAdd(out, (sp + 5e-5f * sq) * (1.0f / BATCH));  // + L2_REG*0.5/BATCH
    }
}

extern "C" void kernel_launch(void* const* d_in, const int* in_sizes, int n_in,
                              void* d_out, int out_size) {
    const float* emb  = (const float*)d_in[0];
    const int*   edge = (const int*)d_in[1];
    const int*   src  = edge;
    const int*   dst  = edge + N_EDGES;
    const int*   user = (const int*)d_in[2];
    const int*   pos  = (const int*)d_in[3];
    const int*   neg  = (const int*)d_in[4];
    float*       out  = (float*)d_out;

    static cudaStream_t s1 = nullptr, s2 = nullptr, s3 = nullptr;
    static cudaEvent_t evInit, evMark, evA, evB, evZ, evP1, evConv;
    if (!s1) {
        cudaStreamCreateWithFlags(&s1, cudaStreamNonBlocking);
        cudaStreamCreateWithFlags(&s2, cudaStreamNonBlocking);
        cudaStreamCreateWithFlags(&s3, cudaStreamNonBlocking);
        cudaEventCreateWithFlags(&evInit, cudaEventDisableTiming);
        cudaEventCreateWithFlags(&evMark, cudaEventDisableTiming);
        cudaEventCreateWithFlags(&evA,    cudaEventDisableTiming);
        cudaEventCreateWithFlags(&evB,    cudaEventDisableTiming);
        cudaEventCreateWithFlags(&evZ,    cudaEventDisableTiming);
        cudaEventCreateWithFlags(&evP1,   cudaEventDisableTiming);
        cudaEventCreateWithFlags(&evConv, cudaEventDisableTiming);
    }

    const int T = 256;
    const int G_NODES = (N_NODES + T - 1) / T;
    const int G_EDGES = (N_EDGES + T - 1) / T;
    const int G_CMP   = (N_EDGES / 8 + T - 1) / T;
    const int G_MARK  = (9 * BATCH + T - 1) / T;
    const int G_CONV  = (N_NODES * (DIM / 8) + T - 1) / T;
    const int G_PROP  = 2048;
    const int G_ZERO  = 1024;

    // origin stream: serial critical chain (init -> mark -> compacts)
    k_init<<<G_NODES, T>>>();
    cudaEventRecord(evInit, 0);
    k_mark_batch<<<G_MARK, T>>>(user, pos, neg);
    cudaEventRecord(evMark, 0);
    k_compact8s<<<G_CMP, T>>>(src, dst, 2, -1, 1, 1); // f2 edges -> list2; mark fb1 (+nl1)
    cudaEventRecord(evA, 0);
    k_compact8s<<<G_CMP, T>>>(src, dst, 1, -1, 0, 1); // f1 edges -> list1; mark fb0 (+nl0)
    cudaEventRecord(evB, 0);
    // compactC overlapped with prop1a on s1: only f0 && !f1 edges
    k_compact8s<<<G_CMP, T>>>(src, dst, 0, 1, 0, 0);  // -> list0

    // s3: emb -> bf16 conversion (independent of everything but init slot)
    cudaStreamWaitEvent(s3, evInit, 0);
    k_conv<<<G_CONV, T, 0, s3>>>(emb);
    cudaEventRecord(evConv, s3);

    // s1: deg -> dinv (needed by props)
    cudaStreamWaitEvent(s1, evInit, 0);
    k_deg<<<G_EDGES, T, 0, s1>>>(dst);
    k_dinv<<<G_NODES, T, 0, s1>>>();

    // s2: zeros as node lists finalize (joins capture via event-wait first)
    cudaStreamWaitEvent(s2, evMark, 0);
    k_zero_out<<<1, 1, 0, s2>>>(out);
    k_zero_list<<<G_ZERO, T, 0, s2>>>(3, 2);        // XC over nl2
    cudaStreamWaitEvent(s2, evA, 0);
    k_zero_list<<<G_ZERO, T, 0, s2>>>(2, 1);        // XB over nl1
    cudaStreamWaitEvent(s2, evB, 0);
    k_zero_list<<<G_ZERO, T, 0, s2>>>(1, 0);        // XA over nl0
    cudaEventRecord(evZ, s2);

    // prop1a on s1: EB -> XA over list1 edges (list1 ⊆ layer-1 edge set),
    // overlapped with compactC on origin
    cudaStreamWaitEvent(s1, evZ, 0);
    cudaStreamWaitEvent(s1, evConv, 0);
    k_prop_list<<<G_PROP, T, 0, s1>>>(0, 1, 1);
    cudaEventRecord(evP1, s1);

    // join onto origin
    cudaStreamWaitEvent(0, evZ, 0);
    cudaStreamWaitEvent(0, evP1, 0);

    // prop1b: remaining layer-1 edges (f0 && !f1) -> XA
    k_prop_list<<<G_PROP, T>>>(0, 1, 0);
    // layers 2/3
    k_prop_list<<<G_PROP, T>>>(1, 2, 1);            // XA -> XB over list1
    k_prop_list<<<G_PROP, T>>>(2, 3, 2);            // XB -> XC over list2

    // fused loss
    k_loss<<<BATCH / 8, T>>>(emb, user, pos, neg, out);
}